// round 7
// baseline (speedup 1.0000x reference)
#include <cuda_runtime.h>
#include <math.h>

#define HS    3072
#define MOD6  (6*HS)
#define MLPD  12288
#define NH    24
#define HD    128
#define LIMG  2048
#define LTXT  512
#define LTOT  2560
#define LEPS  1e-6f

// ---------------- scratch (device globals; no runtime allocation) ----------------
static __device__ float g_sv[HS];
static __device__ float g_mod_img[MOD6];
static __device__ float g_mod_txt[MOD6];
static __device__ float g_tmp_img[(size_t)LIMG*HS];
static __device__ float g_tmp_txt[(size_t)LTXT*HS];
static __device__ float g_qkv_img[(size_t)LIMG*3*HS];
static __device__ float g_qkv_txt[(size_t)LTXT*3*HS];
static __device__ float g_q[(size_t)NH*LTOT*HD];
static __device__ float g_k[(size_t)NH*LTOT*HD];
static __device__ float g_v[(size_t)NH*LTOT*HD];
static __device__ float g_attn[(size_t)LTOT*HS];
static __device__ float g_ximg[(size_t)LIMG*HS];
static __device__ float g_xtxt[(size_t)LTXT*HS];
static __device__ float g_hid_img[(size_t)LIMG*MLPD];
static __device__ float g_hid_txt[(size_t)LTXT*MLPD];

// ---------------- helpers ----------------
__device__ __forceinline__ float gelu_tanh(float x) {
    float c = x + 0.044715f * x * x * x;
    return 0.5f * x * (1.f + tanhf(0.7978845608028654f * c));
}

// ---------------- silu(vec) ----------------
__global__ void k_silu(const float* __restrict__ vec) {
    int i = blockIdx.x * 256 + threadIdx.x;
    if (i < HS) {
        float v = vec[i];
        g_sv[i] = v / (1.f + expf(-v));
    }
}

// ---------------- mod = silu(vec) @ W + b  (K=3072 -> N=18432) ----------------
__global__ void k_modlin(const float* __restrict__ w, const float* __restrict__ b,
                         float* __restrict__ out) {
    __shared__ float sv[HS];
    for (int i = threadIdx.x; i < HS; i += 128) sv[i] = g_sv[i];
    __syncthreads();
    int n = blockIdx.x * 128 + threadIdx.x;
    const float* wp = w + n;
    float a0 = 0.f, a1 = 0.f, a2 = 0.f, a3 = 0.f;
    for (int k = 0; k < HS; k += 4) {
        a0 += sv[k+0] * wp[(size_t)(k+0) * MOD6];
        a1 += sv[k+1] * wp[(size_t)(k+1) * MOD6];
        a2 += sv[k+2] * wp[(size_t)(k+2) * MOD6];
        a3 += sv[k+3] * wp[(size_t)(k+3) * MOD6];
    }
    out[n] = (a0 + a1) + (a2 + a3) + b[n];
}

// ---------------- out = shift + (1+scale) * LN(x), one block per row ----------------
__global__ void k_lnmod(const float* __restrict__ x, const float* __restrict__ mod,
                        int shift_off, float* __restrict__ out) {
    const int row = blockIdx.x;
    const int t = threadIdx.x;
    const float* xr = x + (size_t)row * HS;
    float v[12];
    float s = 0.f, sq = 0.f;
    #pragma unroll
    for (int i = 0; i < 12; i++) {
        v[i] = xr[t + i * 256];
        s += v[i];
        sq += v[i] * v[i];
    }
    #pragma unroll
    for (int o = 16; o; o >>= 1) {
        s  += __shfl_xor_sync(0xffffffffu, s, o);
        sq += __shfl_xor_sync(0xffffffffu, sq, o);
    }
    __shared__ float ss[8], ssq[8];
    int w = t >> 5;
    if ((t & 31) == 0) { ss[w] = s; ssq[w] = sq; }
    __syncthreads();
    s = 0.f; sq = 0.f;
    #pragma unroll
    for (int i = 0; i < 8; i++) { s += ss[i]; sq += ssq[i]; }
    float mean = s * (1.f / HS);
    float var  = sq * (1.f / HS) - mean * mean;
    float r = rsqrtf(var + LEPS);
    const float* sh = mod + (size_t)shift_off * HS;
    const float* sc = mod + (size_t)(shift_off + 1) * HS;
    float* orow = out + (size_t)row * HS;
    #pragma unroll
    for (int i = 0; i < 12; i++) {
        int c = t + i * 256;
        orow[c] = sh[c] + (1.f + sc[c]) * (v[i] - mean) * r;
    }
}

// ---------------- SGEMM: C = A(MxK) @ B(KxN), epilogues ----------------
// EPI 0: +bias   EPI 1: gelu(+bias)   EPI 2: res + gate*(+bias)
template<int EPI>
__global__ void __launch_bounds__(256) k_gemm(
    const float* __restrict__ A, const float* __restrict__ B,
    const float* __restrict__ bias, const float* __restrict__ res,
    const float* __restrict__ gate, float* __restrict__ C,
    int M, int N, int K)
{
    __shared__ float As[2][8][132];
    __shared__ float Bs[2][8][132];
    const int tid = threadIdx.x;
    const int tx = tid & 15, ty = tid >> 4;
    const int m0 = blockIdx.y * 128, n0 = blockIdx.x * 128;
    const int arow = tid >> 1, acol = (tid & 1) * 4;
    const int brow = tid >> 5, bcol = (tid & 31) * 4;
    const float* Ap = A + (size_t)(m0 + arow) * K + acol;
    const float* Bp = B + (size_t)brow * N + n0 + bcol;

    float acc[8][8];
    #pragma unroll
    for (int i = 0; i < 8; i++)
        #pragma unroll
        for (int j = 0; j < 8; j++) acc[i][j] = 0.f;

    {
        float4 a = *(const float4*)Ap;
        float4 b = *(const float4*)Bp;
        As[0][acol+0][arow] = a.x; As[0][acol+1][arow] = a.y;
        As[0][acol+2][arow] = a.z; As[0][acol+3][arow] = a.w;
        *(float4*)&Bs[0][brow][bcol] = b;
    }
    __syncthreads();

    const int KT = K >> 3;
    for (int t = 0; t < KT; t++) {
        const int cur = t & 1, nxt = cur ^ 1;
        float4 an, bn;
        if (t + 1 < KT) {
            an = *(const float4*)(Ap + (t + 1) * 8);
            bn = *(const float4*)(Bp + (size_t)(t + 1) * 8 * N);
        }
        #pragma unroll
        for (int k = 0; k < 8; k++) {
            float af[8], bf[8];
            *(float4*)(af)     = *(const float4*)&As[cur][k][ty * 8];
            *(float4*)(af + 4) = *(const float4*)&As[cur][k][ty * 8 + 4];
            *(float4*)(bf)     = *(const float4*)&Bs[cur][k][tx * 8];
            *(float4*)(bf + 4) = *(const float4*)&Bs[cur][k][tx * 8 + 4];
            #pragma unroll
            for (int i = 0; i < 8; i++)
                #pragma unroll
                for (int j = 0; j < 8; j++)
                    acc[i][j] = fmaf(af[i], bf[j], acc[i][j]);
        }
        if (t + 1 < KT) {
            As[nxt][acol+0][arow] = an.x; As[nxt][acol+1][arow] = an.y;
            As[nxt][acol+2][arow] = an.z; As[nxt][acol+3][arow] = an.w;
            *(float4*)&Bs[nxt][brow][bcol] = bn;
            __syncthreads();
        }
    }

    #pragma unroll
    for (int i = 0; i < 8; i++) {
        const int row = m0 + ty * 8 + i;
        float* crow = C + (size_t)row * N + n0 + tx * 8;
        const float* rrow = (EPI == 2) ? (res + (size_t)row * N + n0 + tx * 8) : nullptr;
        #pragma unroll
        for (int j = 0; j < 8; j++) {
            const int col = n0 + tx * 8 + j;
            float v = acc[i][j] + bias[col];
            if (EPI == 1) v = gelu_tanh(v);
            if (EPI == 2) v = rrow[j] + gate[col] * v;
            crow[j] = v;
        }
    }
}

// ---------------- QKV post: RMSNorm(q,k) * scale, RoPE, scatter to [H][L][D] ----------------
__global__ void k_qkvpost(const float* __restrict__ pe,
                          const float* __restrict__ iqs, const float* __restrict__ iks,
                          const float* __restrict__ tqs, const float* __restrict__ tks) {
    const int t = blockIdx.x;   // token in [0, LTOT): txt first, then img
    const int h = blockIdx.y;
    const int d = threadIdx.x;  // 128 threads
    const float* src;
    const float *qs, *ks;
    if (t < LTXT) { src = g_qkv_txt + (size_t)t * 3 * HS; qs = tqs; ks = tks; }
    else          { src = g_qkv_img + (size_t)(t - LTXT) * 3 * HS; qs = iqs; ks = iks; }
    float qv = src[h * HD + d];
    float kv = src[HS + h * HD + d];
    float vv = src[2 * HS + h * HD + d];

    float sq = qv * qv, sk = kv * kv;
    #pragma unroll
    for (int o = 16; o; o >>= 1) {
        sq += __shfl_xor_sync(0xffffffffu, sq, o);
        sk += __shfl_xor_sync(0xffffffffu, sk, o);
    }
    __shared__ float aq[4], ak[4];
    int w = d >> 5;
    if ((d & 31) == 0) { aq[w] = sq; ak[w] = sk; }
    __syncthreads();
    sq = aq[0] + aq[1] + aq[2] + aq[3];
    sk = ak[0] + ak[1] + ak[2] + ak[3];
    float rq = rsqrtf(sq * (1.f / HD) + LEPS);
    float rk = rsqrtf(sk * (1.f / HD) + LEPS);
    qv *= rq * qs[d];
    kv *= rk * ks[d];

    // RoPE on consecutive pairs; partner = lane ^ 1
    const int kk = d >> 1, odd = d & 1;
    float qo = __shfl_xor_sync(0xffffffffu, qv, 1);
    float ko = __shfl_xor_sync(0xffffffffu, kv, 1);
    const float* p = pe + (size_t)t * 256 + kk * 4 + odd * 2;
    float q0 = odd ? qo : qv, q1 = odd ? qv : qo;
    float k0 = odd ? ko : kv, k1 = odd ? kv : ko;
    float qr = p[0] * q0 + p[1] * q1;
    float kr = p[0] * k0 + p[1] * k1;

    size_t o = ((size_t)h * LTOT + t) * HD + d;
    g_q[o] = qr; g_k[o] = kr; g_v[o] = vv;
}

// ---------------- flash attention: 64-query tile per block, online softmax ----------------
__global__ void __launch_bounds__(256) k_attn() {
    extern __shared__ float sm[];
    float* Qs = sm;              // 64*128
    float* Ks = Qs + 64 * 128;   // 64*132 (padded)
    float* Vs = Ks + 64 * 132;   // 64*132 (padded)
    float* Ps = Vs + 64 * 132;   // 64*64
    const int h  = blockIdx.y;
    const int q0 = blockIdx.x * 64;
    const int tid = threadIdx.x;
    const int rg = tid >> 4, cg = tid & 15;
    const int r0 = rg * 4, c0 = cg * 4, oc0 = cg * 8;

    const float* Qg = g_q + ((size_t)h * LTOT + q0) * HD;
    for (int i = tid; i < 64 * HD / 4; i += 256)
        ((float4*)Qs)[i] = ((const float4*)Qg)[i];

    float mrow[4] = {-INFINITY, -INFINITY, -INFINITY, -INFINITY};
    float lrow[4] = {0.f, 0.f, 0.f, 0.f};
    float O[4][8];
    #pragma unroll
    for (int i = 0; i < 4; i++)
        #pragma unroll
        for (int j = 0; j < 8; j++) O[i][j] = 0.f;
    const float scale = 0.08838834764831845f;  // 1/sqrt(128)

    for (int kt = 0; kt < LTOT / 64; kt++) {
        const float* Kg = g_k + ((size_t)h * LTOT + kt * 64) * HD;
        const float* Vg = g_v + ((size_t)h * LTOT + kt * 64) * HD;
        __syncthreads();  // previous tile fully consumed
        for (int i = tid; i < 64 * HD / 4; i += 256) {
            int row = i >> 5, col4 = (i & 31) * 4;
            *(float4*)&Ks[row * 132 + col4] = ((const float4*)Kg)[i];
            *(float4*)&Vs[row * 132 + col4] = ((const float4*)Vg)[i];
        }
        __syncthreads();

        float S[4][4] = {};
        #pragma unroll 4
        for (int d4 = 0; d4 < 32; d4++) {
            float4 qf[4], kf[4];
            #pragma unroll
            for (int i = 0; i < 4; i++) qf[i] = *(const float4*)&Qs[(r0 + i) * 128 + d4 * 4];
            #pragma unroll
            for (int j = 0; j < 4; j++) kf[j] = *(const float4*)&Ks[(c0 + j) * 132 + d4 * 4];
            #pragma unroll
            for (int i = 0; i < 4; i++)
                #pragma unroll
                for (int j = 0; j < 4; j++)
                    S[i][j] += qf[i].x * kf[j].x + qf[i].y * kf[j].y +
                               qf[i].z * kf[j].z + qf[i].w * kf[j].w;
        }

        float alpha[4];
        #pragma unroll
        for (int i = 0; i < 4; i++) {
            float mx = fmaxf(fmaxf(S[i][0], S[i][1]), fmaxf(S[i][2], S[i][3])) * scale;
            #pragma unroll
            for (int o = 8; o; o >>= 1) mx = fmaxf(mx, __shfl_xor_sync(0xffffffffu, mx, o));
            const float mn = fmaxf(mrow[i], mx);
            float rs = 0.f;
            #pragma unroll
            for (int j = 0; j < 4; j++) {
                float pv = __expf(S[i][j] * scale - mn);
                Ps[(r0 + i) * 64 + c0 + j] = pv;
                rs += pv;
            }
            #pragma unroll
            for (int o = 8; o; o >>= 1) rs += __shfl_xor_sync(0xffffffffu, rs, o);
            alpha[i] = __expf(mrow[i] - mn);
            lrow[i] = lrow[i] * alpha[i] + rs;
            mrow[i] = mn;
        }
        __syncthreads();  // Ps visible to all

        #pragma unroll
        for (int i = 0; i < 4; i++)
            #pragma unroll
            for (int jj = 0; jj < 8; jj++) O[i][jj] *= alpha[i];

        #pragma unroll 2
        for (int j = 0; j < 64; j++) {
            float4 v0 = *(const float4*)&Vs[j * 132 + oc0];
            float4 v1 = *(const float4*)&Vs[j * 132 + oc0 + 4];
            #pragma unroll
            for (int i = 0; i < 4; i++) {
                float pv = Ps[(r0 + i) * 64 + j];
                O[i][0] = fmaf(pv, v0.x, O[i][0]);
                O[i][1] = fmaf(pv, v0.y, O[i][1]);
                O[i][2] = fmaf(pv, v0.z, O[i][2]);
                O[i][3] = fmaf(pv, v0.w, O[i][3]);
                O[i][4] = fmaf(pv, v1.x, O[i][4]);
                O[i][5] = fmaf(pv, v1.y, O[i][5]);
                O[i][6] = fmaf(pv, v1.z, O[i][6]);
                O[i][7] = fmaf(pv, v1.w, O[i][7]);
            }
        }
    }

    #pragma unroll
    for (int i = 0; i < 4; i++) {
        float inv = 1.f / lrow[i];
        float* orow = g_attn + (size_t)(q0 + r0 + i) * HS + h * HD + oc0;
        float4 o0 = make_float4(O[i][0] * inv, O[i][1] * inv, O[i][2] * inv, O[i][3] * inv);
        float4 o1 = make_float4(O[i][4] * inv, O[i][5] * inv, O[i][6] * inv, O[i][7] * inv);
        *(float4*)orow = o0;
        *(float4*)(orow + 4) = o1;
    }
}

// ---------------- host launcher ----------------
extern "C" void kernel_launch(void* const* d_in, const int* in_sizes, int n_in,
                              void* d_out, int out_size)
{
    (void)in_sizes; (void)n_in; (void)out_size;
    const float* img      = (const float*)d_in[0];
    const float* txt      = (const float*)d_in[1];
    const float* vec      = (const float*)d_in[2];
    const float* pe       = (const float*)d_in[3];
    const float* i_mod_w  = (const float*)d_in[4];
    const float* i_mod_b  = (const float*)d_in[5];
    const float* i_qkv_w  = (const float*)d_in[6];
    const float* i_qkv_b  = (const float*)d_in[7];
    const float* i_qs     = (const float*)d_in[8];
    const float* i_ks     = (const float*)d_in[9];
    const float* i_proj_w = (const float*)d_in[10];
    const float* i_proj_b = (const float*)d_in[11];
    const float* i_w1     = (const float*)d_in[12];
    const float* i_b1     = (const float*)d_in[13];
    const float* i_w2     = (const float*)d_in[14];
    const float* i_b2     = (const float*)d_in[15];
    const float* t_mod_w  = (const float*)d_in[16];
    const float* t_mod_b  = (const float*)d_in[17];
    const float* t_qkv_w  = (const float*)d_in[18];
    const float* t_qkv_b  = (const float*)d_in[19];
    const float* t_qs     = (const float*)d_in[20];
    const float* t_ks     = (const float*)d_in[21];
    const float* t_proj_w = (const float*)d_in[22];
    const float* t_proj_b = (const float*)d_in[23];
    const float* t_w1     = (const float*)d_in[24];
    const float* t_b1     = (const float*)d_in[25];
    const float* t_w2     = (const float*)d_in[26];
    const float* t_b2     = (const float*)d_in[27];
    float* out = (float*)d_out;

    float *p_mod_img, *p_mod_txt, *p_tmp_img, *p_tmp_txt, *p_qkv_img, *p_qkv_txt;
    float *p_attn, *p_ximg, *p_xtxt, *p_hid_img, *p_hid_txt;
    cudaGetSymbolAddress((void**)&p_mod_img, g_mod_img);
    cudaGetSymbolAddress((void**)&p_mod_txt, g_mod_txt);
    cudaGetSymbolAddress((void**)&p_tmp_img, g_tmp_img);
    cudaGetSymbolAddress((void**)&p_tmp_txt, g_tmp_txt);
    cudaGetSymbolAddress((void**)&p_qkv_img, g_qkv_img);
    cudaGetSymbolAddress((void**)&p_qkv_txt, g_qkv_txt);
    cudaGetSymbolAddress((void**)&p_attn,    g_attn);
    cudaGetSymbolAddress((void**)&p_ximg,    g_ximg);
    cudaGetSymbolAddress((void**)&p_xtxt,    g_xtxt);
    cudaGetSymbolAddress((void**)&p_hid_img, g_hid_img);
    cudaGetSymbolAddress((void**)&p_hid_txt, g_hid_txt);

    const int ATTN_SMEM = (64 * 128 + 2 * 64 * 132 + 64 * 64) * 4;  // 116736 B
    cudaFuncSetAttribute(k_attn, cudaFuncAttributeMaxDynamicSharedMemorySize, ATTN_SMEM);

    // 1) modulation vectors
    k_silu<<<12, 256>>>(vec);
    k_modlin<<<144, 128>>>(i_mod_w, i_mod_b, p_mod_img);
    k_modlin<<<144, 128>>>(t_mod_w, t_mod_b, p_mod_txt);

    // 2) LN + modulate (shift s1 @ offset 0, scale sc1 @ offset 1)
    k_lnmod<<<LIMG, 256>>>(img, p_mod_img, 0, p_tmp_img);
    k_lnmod<<<LTXT, 256>>>(txt, p_mod_txt, 0, p_tmp_txt);

    // 3) QKV GEMMs
    k_gemm<0><<<dim3(72, 16), 256>>>(p_tmp_img, i_qkv_w, i_qkv_b, nullptr, nullptr,
                                     p_qkv_img, LIMG, 3 * HS, HS);
    k_gemm<0><<<dim3(72, 4), 256>>>(p_tmp_txt, t_qkv_w, t_qkv_b, nullptr, nullptr,
                                    p_qkv_txt, LTXT, 3 * HS, HS);

    // 4) RMS + RoPE + head scatter
    k_qkvpost<<<dim3(LTOT, NH), 128>>>(pe, i_qs, i_ks, t_qs, t_ks);

    // 5) attention
    k_attn<<<dim3(LTOT / 64, NH), 256, ATTN_SMEM>>>();

    // 6) proj + gate*g1 + residual
    k_gemm<2><<<dim3(24, 16), 256>>>(p_attn + (size_t)LTXT * HS, i_proj_w, i_proj_b,
                                     img, p_mod_img + 2 * HS, p_ximg, LIMG, HS, HS);
    k_gemm<2><<<dim3(24, 4), 256>>>(p_attn, t_proj_w, t_proj_b,
                                    txt, p_mod_txt + 2 * HS, p_xtxt, LTXT, HS, HS);

    // 7) second LN + modulate (shift s2 @ offset 3, scale sc2 @ offset 4)
    k_lnmod<<<LIMG, 256>>>(p_ximg, p_mod_img, 3, p_tmp_img);
    k_lnmod<<<LTXT, 256>>>(p_xtxt, p_mod_txt, 3, p_tmp_txt);

    // 8) MLP up + gelu
    k_gemm<1><<<dim3(96, 16), 256>>>(p_tmp_img, i_w1, i_b1, nullptr, nullptr,
                                     p_hid_img, LIMG, MLPD, HS);
    k_gemm<1><<<dim3(96, 4), 256>>>(p_tmp_txt, t_w1, t_b1, nullptr, nullptr,
                                    p_hid_txt, LTXT, MLPD, HS);

    // 9) MLP down + gate*g2 + residual, write final outputs (img then txt)
    k_gemm<2><<<dim3(24, 16), 256>>>(p_hid_img, i_w2, i_b2, p_ximg,
                                     p_mod_img + 5 * HS, out, LIMG, HS, MLPD);
    k_gemm<2><<<dim3(24, 4), 256>>>(p_hid_txt, t_w2, t_b2, p_xtxt,
                                    p_mod_txt + 5 * HS, out + (size_t)LIMG * HS,
                                    LTXT, HS, MLPD);
}

// round 8
// speedup vs baseline: 1.0032x; 1.0032x over previous
#include <cuda_runtime.h>
#include <math.h>

#define HS    3072
#define MOD6  (6*HS)
#define MLPD  12288
#define NH    24
#define HD    128
#define LIMG  2048
#define LTXT  512
#define LTOT  2560
#define LEPS  1e-6f

// ---------------- scratch (device globals; no runtime allocation) ----------------
static __device__ float g_sv[HS];
static __device__ float g_mod_img[MOD6];
static __device__ float g_mod_txt[MOD6];
static __device__ float g_tmp_img[(size_t)LIMG*HS];
static __device__ float g_tmp_txt[(size_t)LTXT*HS];
static __device__ float g_qkv_img[(size_t)LIMG*3*HS];
static __device__ float g_qkv_txt[(size_t)LTXT*3*HS];
static __device__ float g_q[(size_t)NH*LTOT*HD];
static __device__ float g_k[(size_t)NH*LTOT*HD];
static __device__ float g_v[(size_t)NH*LTOT*HD];
static __device__ float g_attn[(size_t)LTOT*HS];
static __device__ float g_ximg[(size_t)LIMG*HS];
static __device__ float g_xtxt[(size_t)LTXT*HS];
static __device__ float g_hid_img[(size_t)LIMG*MLPD];
static __device__ float g_hid_txt[(size_t)LTXT*MLPD];

// ---------------- helpers ----------------
__device__ __forceinline__ float gelu_tanh(float x) {
    float c = x + 0.044715f * x * x * x;
    return 0.5f * x * (1.f + tanhf(0.7978845608028654f * c));
}

// ---------------- silu(vec) ----------------
__global__ void k_silu(const float* __restrict__ vec) {
    int i = blockIdx.x * 256 + threadIdx.x;
    if (i < HS) {
        float v = vec[i];
        g_sv[i] = v / (1.f + expf(-v));
    }
}

// ---------------- mod = silu(vec) @ W + b  (K=3072 -> N=18432) ----------------
__global__ void k_modlin(const float* __restrict__ w, const float* __restrict__ b,
                         float* __restrict__ out) {
    __shared__ float sv[HS];
    for (int i = threadIdx.x; i < HS; i += 128) sv[i] = g_sv[i];
    __syncthreads();
    int n = blockIdx.x * 128 + threadIdx.x;
    const float* wp = w + n;
    float a0 = 0.f, a1 = 0.f, a2 = 0.f, a3 = 0.f;
    for (int k = 0; k < HS; k += 4) {
        a0 += sv[k+0] * wp[(size_t)(k+0) * MOD6];
        a1 += sv[k+1] * wp[(size_t)(k+1) * MOD6];
        a2 += sv[k+2] * wp[(size_t)(k+2) * MOD6];
        a3 += sv[k+3] * wp[(size_t)(k+3) * MOD6];
    }
    out[n] = (a0 + a1) + (a2 + a3) + b[n];
}

// ---------------- out = shift + (1+scale) * LN(x), one block per row ----------------
__global__ void k_lnmod(const float* __restrict__ x, const float* __restrict__ mod,
                        int shift_off, float* __restrict__ out) {
    const int row = blockIdx.x;
    const int t = threadIdx.x;
    const float* xr = x + (size_t)row * HS;
    float v[12];
    float s = 0.f, sq = 0.f;
    #pragma unroll
    for (int i = 0; i < 12; i++) {
        v[i] = xr[t + i * 256];
        s += v[i];
        sq += v[i] * v[i];
    }
    #pragma unroll
    for (int o = 16; o; o >>= 1) {
        s  += __shfl_xor_sync(0xffffffffu, s, o);
        sq += __shfl_xor_sync(0xffffffffu, sq, o);
    }
    __shared__ float ss[8], ssq[8];
    int w = t >> 5;
    if ((t & 31) == 0) { ss[w] = s; ssq[w] = sq; }
    __syncthreads();
    s = 0.f; sq = 0.f;
    #pragma unroll
    for (int i = 0; i < 8; i++) { s += ss[i]; sq += ssq[i]; }
    float mean = s * (1.f / HS);
    float var  = sq * (1.f / HS) - mean * mean;
    float r = rsqrtf(var + LEPS);
    const float* sh = mod + (size_t)shift_off * HS;
    const float* sc = mod + (size_t)(shift_off + 1) * HS;
    float* orow = out + (size_t)row * HS;
    #pragma unroll
    for (int i = 0; i < 12; i++) {
        int c = t + i * 256;
        orow[c] = sh[c] + (1.f + sc[c]) * (v[i] - mean) * r;
    }
}

// ---------------- SGEMM: C = A(MxK) @ B(KxN), epilogues ----------------
// EPI 0: +bias   EPI 1: gelu(+bias)   EPI 2: res + gate*(+bias)
template<int EPI>
__global__ void __launch_bounds__(256) k_gemm(
    const float* __restrict__ A, const float* __restrict__ B,
    const float* __restrict__ bias, const float* __restrict__ res,
    const float* __restrict__ gate, float* __restrict__ C,
    int M, int N, int K)
{
    __shared__ float As[2][8][132];
    __shared__ float Bs[2][8][132];
    const int tid = threadIdx.x;
    const int tx = tid & 15, ty = tid >> 4;
    const int m0 = blockIdx.y * 128, n0 = blockIdx.x * 128;
    const int arow = tid >> 1, acol = (tid & 1) * 4;
    const int brow = tid >> 5, bcol = (tid & 31) * 4;
    const float* Ap = A + (size_t)(m0 + arow) * K + acol;
    const float* Bp = B + (size_t)brow * N + n0 + bcol;

    float acc[8][8];
    #pragma unroll
    for (int i = 0; i < 8; i++)
        #pragma unroll
        for (int j = 0; j < 8; j++) acc[i][j] = 0.f;

    {
        float4 a = *(const float4*)Ap;
        float4 b = *(const float4*)Bp;
        As[0][acol+0][arow] = a.x; As[0][acol+1][arow] = a.y;
        As[0][acol+2][arow] = a.z; As[0][acol+3][arow] = a.w;
        *(float4*)&Bs[0][brow][bcol] = b;
    }
    __syncthreads();

    const int KT = K >> 3;
    for (int t = 0; t < KT; t++) {
        const int cur = t & 1, nxt = cur ^ 1;
        float4 an, bn;
        if (t + 1 < KT) {
            an = *(const float4*)(Ap + (t + 1) * 8);
            bn = *(const float4*)(Bp + (size_t)(t + 1) * 8 * N);
        }
        #pragma unroll
        for (int k = 0; k < 8; k++) {
            float af[8], bf[8];
            *(float4*)(af)     = *(const float4*)&As[cur][k][ty * 8];
            *(float4*)(af + 4) = *(const float4*)&As[cur][k][ty * 8 + 4];
            *(float4*)(bf)     = *(const float4*)&Bs[cur][k][tx * 8];
            *(float4*)(bf + 4) = *(const float4*)&Bs[cur][k][tx * 8 + 4];
            #pragma unroll
            for (int i = 0; i < 8; i++)
                #pragma unroll
                for (int j = 0; j < 8; j++)
                    acc[i][j] = fmaf(af[i], bf[j], acc[i][j]);
        }
        if (t + 1 < KT) {
            As[nxt][acol+0][arow] = an.x; As[nxt][acol+1][arow] = an.y;
            As[nxt][acol+2][arow] = an.z; As[nxt][acol+3][arow] = an.w;
            *(float4*)&Bs[nxt][brow][bcol] = bn;
            __syncthreads();
        }
    }

    #pragma unroll
    for (int i = 0; i < 8; i++) {
        const int row = m0 + ty * 8 + i;
        float* crow = C + (size_t)row * N + n0 + tx * 8;
        const float* rrow = (EPI == 2) ? (res + (size_t)row * N + n0 + tx * 8) : nullptr;
        #pragma unroll
        for (int j = 0; j < 8; j++) {
            const int col = n0 + tx * 8 + j;
            float v = acc[i][j] + bias[col];
            if (EPI == 1) v = gelu_tanh(v);
            if (EPI == 2) v = rrow[j] + gate[col] * v;
            crow[j] = v;
        }
    }
}

// ---------------- QKV post: RMSNorm(q,k) * scale, RoPE, scatter to [H][L][D] ----------------
__global__ void k_qkvpost(const float* __restrict__ pe,
                          const float* __restrict__ iqs, const float* __restrict__ iks,
                          const float* __restrict__ tqs, const float* __restrict__ tks) {
    const int t = blockIdx.x;   // token in [0, LTOT): txt first, then img
    const int h = blockIdx.y;
    const int d = threadIdx.x;  // 128 threads
    const float* src;
    const float *qs, *ks;
    if (t < LTXT) { src = g_qkv_txt + (size_t)t * 3 * HS; qs = tqs; ks = tks; }
    else          { src = g_qkv_img + (size_t)(t - LTXT) * 3 * HS; qs = iqs; ks = iks; }
    float qv = src[h * HD + d];
    float kv = src[HS + h * HD + d];
    float vv = src[2 * HS + h * HD + d];

    float sq = qv * qv, sk = kv * kv;
    #pragma unroll
    for (int o = 16; o; o >>= 1) {
        sq += __shfl_xor_sync(0xffffffffu, sq, o);
        sk += __shfl_xor_sync(0xffffffffu, sk, o);
    }
    __shared__ float aq[4], ak[4];
    int w = d >> 5;
    if ((d & 31) == 0) { aq[w] = sq; ak[w] = sk; }
    __syncthreads();
    sq = aq[0] + aq[1] + aq[2] + aq[3];
    sk = ak[0] + ak[1] + ak[2] + ak[3];
    float rq = rsqrtf(sq * (1.f / HD) + LEPS);
    float rk = rsqrtf(sk * (1.f / HD) + LEPS);
    qv *= rq * qs[d];
    kv *= rk * ks[d];

    // RoPE on consecutive pairs; partner = lane ^ 1
    const int kk = d >> 1, odd = d & 1;
    float qo = __shfl_xor_sync(0xffffffffu, qv, 1);
    float ko = __shfl_xor_sync(0xffffffffu, kv, 1);
    const float* p = pe + (size_t)t * 256 + kk * 4 + odd * 2;
    float q0 = odd ? qo : qv, q1 = odd ? qv : qo;
    float k0 = odd ? ko : kv, k1 = odd ? kv : ko;
    float qr = p[0] * q0 + p[1] * q1;
    float kr = p[0] * k0 + p[1] * k1;

    size_t o = ((size_t)h * LTOT + t) * HD + d;
    g_q[o] = qr; g_k[o] = kr; g_v[o] = vv;
}

// ---------------- flash attention: 64-query tile per block, online softmax ----------------
__global__ void __launch_bounds__(256) k_attn() {
    extern __shared__ float sm[];
    float* Qs = sm;              // 64*128
    float* Ks = Qs + 64 * 128;   // 64*132 (padded)
    float* Vs = Ks + 64 * 132;   // 64*132 (padded)
    float* Ps = Vs + 64 * 132;   // 64*64
    const int h  = blockIdx.y;
    const int q0 = blockIdx.x * 64;
    const int tid = threadIdx.x;
    const int rg = tid >> 4, cg = tid & 15;
    const int r0 = rg * 4, c0 = cg * 4, oc0 = cg * 8;

    const float* Qg = g_q + ((size_t)h * LTOT + q0) * HD;
    for (int i = tid; i < 64 * HD / 4; i += 256)
        ((float4*)Qs)[i] = ((const float4*)Qg)[i];

    float mrow[4] = {-INFINITY, -INFINITY, -INFINITY, -INFINITY};
    float lrow[4] = {0.f, 0.f, 0.f, 0.f};
    float O[4][8];
    #pragma unroll
    for (int i = 0; i < 4; i++)
        #pragma unroll
        for (int j = 0; j < 8; j++) O[i][j] = 0.f;
    const float scale = 0.08838834764831845f;  // 1/sqrt(128)

    for (int kt = 0; kt < LTOT / 64; kt++) {
        const float* Kg = g_k + ((size_t)h * LTOT + kt * 64) * HD;
        const float* Vg = g_v + ((size_t)h * LTOT + kt * 64) * HD;
        __syncthreads();  // previous tile fully consumed
        for (int i = tid; i < 64 * HD / 4; i += 256) {
            int row = i >> 5, col4 = (i & 31) * 4;
            *(float4*)&Ks[row * 132 + col4] = ((const float4*)Kg)[i];
            *(float4*)&Vs[row * 132 + col4] = ((const float4*)Vg)[i];
        }
        __syncthreads();

        float S[4][4] = {};
        #pragma unroll 4
        for (int d4 = 0; d4 < 32; d4++) {
            float4 qf[4], kf[4];
            #pragma unroll
            for (int i = 0; i < 4; i++) qf[i] = *(const float4*)&Qs[(r0 + i) * 128 + d4 * 4];
            #pragma unroll
            for (int j = 0; j < 4; j++) kf[j] = *(const float4*)&Ks[(c0 + j) * 132 + d4 * 4];
            #pragma unroll
            for (int i = 0; i < 4; i++)
                #pragma unroll
                for (int j = 0; j < 4; j++)
                    S[i][j] += qf[i].x * kf[j].x + qf[i].y * kf[j].y +
                               qf[i].z * kf[j].z + qf[i].w * kf[j].w;
        }

        float alpha[4];
        #pragma unroll
        for (int i = 0; i < 4; i++) {
            float mx = fmaxf(fmaxf(S[i][0], S[i][1]), fmaxf(S[i][2], S[i][3])) * scale;
            #pragma unroll
            for (int o = 8; o; o >>= 1) mx = fmaxf(mx, __shfl_xor_sync(0xffffffffu, mx, o));
            const float mn = fmaxf(mrow[i], mx);
            float rs = 0.f;
            #pragma unroll
            for (int j = 0; j < 4; j++) {
                float pv = __expf(S[i][j] * scale - mn);
                Ps[(r0 + i) * 64 + c0 + j] = pv;
                rs += pv;
            }
            #pragma unroll
            for (int o = 8; o; o >>= 1) rs += __shfl_xor_sync(0xffffffffu, rs, o);
            alpha[i] = __expf(mrow[i] - mn);
            lrow[i] = lrow[i] * alpha[i] + rs;
            mrow[i] = mn;
        }
        __syncthreads();  // Ps visible to all

        #pragma unroll
        for (int i = 0; i < 4; i++)
            #pragma unroll
            for (int jj = 0; jj < 8; jj++) O[i][jj] *= alpha[i];

        #pragma unroll 2
        for (int j = 0; j < 64; j++) {
            float4 v0 = *(const float4*)&Vs[j * 132 + oc0];
            float4 v1 = *(const float4*)&Vs[j * 132 + oc0 + 4];
            #pragma unroll
            for (int i = 0; i < 4; i++) {
                float pv = Ps[(r0 + i) * 64 + j];
                O[i][0] = fmaf(pv, v0.x, O[i][0]);
                O[i][1] = fmaf(pv, v0.y, O[i][1]);
                O[i][2] = fmaf(pv, v0.z, O[i][2]);
                O[i][3] = fmaf(pv, v0.w, O[i][3]);
                O[i][4] = fmaf(pv, v1.x, O[i][4]);
                O[i][5] = fmaf(pv, v1.y, O[i][5]);
                O[i][6] = fmaf(pv, v1.z, O[i][6]);
                O[i][7] = fmaf(pv, v1.w, O[i][7]);
            }
        }
    }

    #pragma unroll
    for (int i = 0; i < 4; i++) {
        float inv = 1.f / lrow[i];
        float* orow = g_attn + (size_t)(q0 + r0 + i) * HS + h * HD + oc0;
        float4 o0 = make_float4(O[i][0] * inv, O[i][1] * inv, O[i][2] * inv, O[i][3] * inv);
        float4 o1 = make_float4(O[i][4] * inv, O[i][5] * inv, O[i][6] * inv, O[i][7] * inv);
        *(float4*)orow = o0;
        *(float4*)(orow + 4) = o1;
    }
}

// ---------------- host launcher ----------------
extern "C" void kernel_launch(void* const* d_in, const int* in_sizes, int n_in,
                              void* d_out, int out_size)
{
    (void)in_sizes; (void)n_in; (void)out_size;
    const float* img      = (const float*)d_in[0];
    const float* txt      = (const float*)d_in[1];
    const float* vec      = (const float*)d_in[2];
    const float* pe       = (const float*)d_in[3];
    const float* i_mod_w  = (const float*)d_in[4];
    const float* i_mod_b  = (const float*)d_in[5];
    const float* i_qkv_w  = (const float*)d_in[6];
    const float* i_qkv_b  = (const float*)d_in[7];
    const float* i_qs     = (const float*)d_in[8];
    const float* i_ks     = (const float*)d_in[9];
    const float* i_proj_w = (const float*)d_in[10];
    const float* i_proj_b = (const float*)d_in[11];
    const float* i_w1     = (const float*)d_in[12];
    const float* i_b1     = (const float*)d_in[13];
    const float* i_w2     = (const float*)d_in[14];
    const float* i_b2     = (const float*)d_in[15];
    const float* t_mod_w  = (const float*)d_in[16];
    const float* t_mod_b  = (const float*)d_in[17];
    const float* t_qkv_w  = (const float*)d_in[18];
    const float* t_qkv_b  = (const float*)d_in[19];
    const float* t_qs     = (const float*)d_in[20];
    const float* t_ks     = (const float*)d_in[21];
    const float* t_proj_w = (const float*)d_in[22];
    const float* t_proj_b = (const float*)d_in[23];
    const float* t_w1     = (const float*)d_in[24];
    const float* t_b1     = (const float*)d_in[25];
    const float* t_w2     = (const float*)d_in[26];
    const float* t_b2     = (const float*)d_in[27];
    float* out = (float*)d_out;

    float *p_mod_img, *p_mod_txt, *p_tmp_img, *p_tmp_txt, *p_qkv_img, *p_qkv_txt;
    float *p_attn, *p_ximg, *p_xtxt, *p_hid_img, *p_hid_txt;
    cudaGetSymbolAddress((void**)&p_mod_img, g_mod_img);
    cudaGetSymbolAddress((void**)&p_mod_txt, g_mod_txt);
    cudaGetSymbolAddress((void**)&p_tmp_img, g_tmp_img);
    cudaGetSymbolAddress((void**)&p_tmp_txt, g_tmp_txt);
    cudaGetSymbolAddress((void**)&p_qkv_img, g_qkv_img);
    cudaGetSymbolAddress((void**)&p_qkv_txt, g_qkv_txt);
    cudaGetSymbolAddress((void**)&p_attn,    g_attn);
    cudaGetSymbolAddress((void**)&p_ximg,    g_ximg);
    cudaGetSymbolAddress((void**)&p_xtxt,    g_xtxt);
    cudaGetSymbolAddress((void**)&p_hid_img, g_hid_img);
    cudaGetSymbolAddress((void**)&p_hid_txt, g_hid_txt);

    const int ATTN_SMEM = (64 * 128 + 2 * 64 * 132 + 64 * 64) * 4;  // 116736 B
    cudaFuncSetAttribute(k_attn, cudaFuncAttributeMaxDynamicSharedMemorySize, ATTN_SMEM);

    // 1) modulation vectors
    k_silu<<<12, 256>>>(vec);
    k_modlin<<<144, 128>>>(i_mod_w, i_mod_b, p_mod_img);
    k_modlin<<<144, 128>>>(t_mod_w, t_mod_b, p_mod_txt);

    // 2) LN + modulate (shift s1 @ offset 0, scale sc1 @ offset 1)
    k_lnmod<<<LIMG, 256>>>(img, p_mod_img, 0, p_tmp_img);
    k_lnmod<<<LTXT, 256>>>(txt, p_mod_txt, 0, p_tmp_txt);

    // 3) QKV GEMMs
    k_gemm<0><<<dim3(72, 16), 256>>>(p_tmp_img, i_qkv_w, i_qkv_b, nullptr, nullptr,
                                     p_qkv_img, LIMG, 3 * HS, HS);
    k_gemm<0><<<dim3(72, 4), 256>>>(p_tmp_txt, t_qkv_w, t_qkv_b, nullptr, nullptr,
                                    p_qkv_txt, LTXT, 3 * HS, HS);

    // 4) RMS + RoPE + head scatter
    k_qkvpost<<<dim3(LTOT, NH), 128>>>(pe, i_qs, i_ks, t_qs, t_ks);

    // 5) attention
    k_attn<<<dim3(LTOT / 64, NH), 256, ATTN_SMEM>>>();

    // 6) proj + gate*g1 + residual
    k_gemm<2><<<dim3(24, 16), 256>>>(p_attn + (size_t)LTXT * HS, i_proj_w, i_proj_b,
                                     img, p_mod_img + 2 * HS, p_ximg, LIMG, HS, HS);
    k_gemm<2><<<dim3(24, 4), 256>>>(p_attn, t_proj_w, t_proj_b,
                                    txt, p_mod_txt + 2 * HS, p_xtxt, LTXT, HS, HS);

    // 7) second LN + modulate (shift s2 @ offset 3, scale sc2 @ offset 4)
    k_lnmod<<<LIMG, 256>>>(p_ximg, p_mod_img, 3, p_tmp_img);
    k_lnmod<<<LTXT, 256>>>(p_xtxt, p_mod_txt, 3, p_tmp_txt);

    // 8) MLP up + gelu
    k_gemm<1><<<dim3(96, 16), 256>>>(p_tmp_img, i_w1, i_b1, nullptr, nullptr,
                                     p_hid_img, LIMG, MLPD, HS);
    k_gemm<1><<<dim3(96, 4), 256>>>(p_tmp_txt, t_w1, t_b1, nullptr, nullptr,
                                    p_hid_txt, LTXT, MLPD, HS);

    // 9) MLP down + gate*g2 + residual, write final outputs (img then txt)
    k_gemm<2><<<dim3(24, 16), 256>>>(p_hid_img, i_w2, i_b2, p_ximg,
                                     p_mod_img + 5 * HS, out, LIMG, HS, MLPD);
    k_gemm<2><<<dim3(24, 4), 256>>>(p_hid_txt, t_w2, t_b2, p_xtxt,
                                    p_mod_txt + 5 * HS, out + (size_t)LIMG * HS,
                                    LTXT, HS, MLPD);
}